// round 11
// baseline (speedup 1.0000x reference)
#include <cuda_runtime.h>
#include <math.h>

#define Bsz 64
#define Tsz 2048
#define Dsz 256
#define Hsz 512
#define Gsz 2048
#define NB  128

typedef unsigned long long u64;

// ---- packed fp32x2 helpers (Blackwell FFMA2/FADD2, PTX-only) ----
__device__ __forceinline__ u64 ffma2(u64 a, u64 b, u64 c) {
    u64 d;
    asm("fma.rn.f32x2 %0, %1, %2, %3;" : "=l"(d) : "l"(a), "l"(b), "l"(c));
    return d;
}
__device__ __forceinline__ u64 fadd2(u64 a, u64 b) {
    u64 d;
    asm("add.rn.f32x2 %0, %1, %2;" : "=l"(d) : "l"(a), "l"(b));
    return d;
}
__device__ __forceinline__ u64 dup2(float x) {
    u64 d;
    asm("mov.b64 %0, {%1, %1};" : "=l"(d) : "r"(__float_as_uint(x)));
    return d;
}
__device__ __forceinline__ float lo2(u64 d) { return __int_as_float((int)(unsigned)(d & 0xffffffffu)); }
__device__ __forceinline__ float hi2(u64 d) { return __int_as_float((int)(unsigned)(d >> 32)); }

// Scratch (device globals)
__device__ float g_xw[(size_t)Tsz * Gsz * Bsz];    // [t][col][b]  1 GiB
__device__ float g_Up[128 * Hsz * 16];             // [cg][k][c16]  4 MB
__device__ float g_h[2 * Hsz * Bsz];               // [parity][j][b]
__device__ unsigned g_cnt2[64];                    // 2 counters, 128B apart

__global__ void reset_bar_k() { if (threadIdx.x < 64) g_cnt2[threadIdx.x] = 0u; }

// g_Up[cg][k][c] = U[k][gate*512 + cg*4 + jj], c = gate*4 + jj (16 cols per cg, cg 0..127)
__global__ void pack_U_k(const float* __restrict__ U) {
    int idx = blockIdx.x * blockDim.x + threadIdx.x;   // 2^20 total
    int c  = idx & 15;
    int k  = (idx >> 4) & (Hsz - 1);
    int cg = idx >> 13;
    g_Up[idx] = U[k * Gsz + (c >> 2) * Hsz + cg * 4 + (c & 3)];
}

// xW GEMM with FFMA2: C[b][col] = sum_k x[b,t,k]*W[k,col] + bias[col] -> [t][col][b]
__global__ __launch_bounds__(256, 2) void gemm_xw_k(const float* __restrict__ x,
                                                    const float* __restrict__ W,
                                                    const float* __restrict__ bias) {
    const int t   = blockIdx.y;
    const int cb  = blockIdx.x;
    const int tid = threadIdx.x;
    __shared__ float As[32 * 68];
    __shared__ float Bs[32 * 132];
    const int b0 = (tid & 15) * 4;
    const int c0 = (tid >> 4) * 8;

    u64 acc[4][4];
    {
        ulonglong2 bb0 = *(const ulonglong2*)(bias + cb * 128 + c0);
        ulonglong2 bb1 = *(const ulonglong2*)(bias + cb * 128 + c0 + 4);
#pragma unroll
        for (int i = 0; i < 4; ++i) {
            acc[i][0] = bb0.x; acc[i][1] = bb0.y;
            acc[i][2] = bb1.x; acc[i][3] = bb1.y;
        }
    }
    const int arow = tid >> 3;
    const int af4  = tid & 7;
    const int wk   = tid >> 3;
    const int wc   = (tid & 7) * 16;

    for (int k0 = 0; k0 < Dsz; k0 += 32) {
#pragma unroll
        for (int pass = 0; pass < 2; ++pass) {
            int b = arow + pass * 32;
            float4 v = *(const float4*)(x + ((size_t)b * Tsz + t) * Dsz + k0 + af4 * 4);
            As[(af4 * 4 + 0) * 68 + b] = v.x;
            As[(af4 * 4 + 1) * 68 + b] = v.y;
            As[(af4 * 4 + 2) * 68 + b] = v.z;
            As[(af4 * 4 + 3) * 68 + b] = v.w;
        }
        const float* wp = W + (size_t)(k0 + wk) * Gsz + cb * 128 + wc;
        float4 w0 = ((const float4*)wp)[0];
        float4 w1 = ((const float4*)wp)[1];
        float4 w2 = ((const float4*)wp)[2];
        float4 w3 = ((const float4*)wp)[3];
        *(float4*)&Bs[wk * 132 + wc + 0]  = w0;
        *(float4*)&Bs[wk * 132 + wc + 4]  = w1;
        *(float4*)&Bs[wk * 132 + wc + 8]  = w2;
        *(float4*)&Bs[wk * 132 + wc + 12] = w3;
        __syncthreads();
#pragma unroll
        for (int kk = 0; kk < 32; ++kk) {
            float4 a = *(const float4*)&As[kk * 68 + b0];
            ulonglong2 u01 = *(const ulonglong2*)&Bs[kk * 132 + c0];
            ulonglong2 u23 = *(const ulonglong2*)&Bs[kk * 132 + c0 + 4];
            u64 a0 = dup2(a.x), a1 = dup2(a.y), a2 = dup2(a.z), a3 = dup2(a.w);
            acc[0][0] = ffma2(a0, u01.x, acc[0][0]);
            acc[1][0] = ffma2(a1, u01.x, acc[1][0]);
            acc[2][0] = ffma2(a2, u01.x, acc[2][0]);
            acc[3][0] = ffma2(a3, u01.x, acc[3][0]);
            acc[0][1] = ffma2(a0, u01.y, acc[0][1]);
            acc[1][1] = ffma2(a1, u01.y, acc[1][1]);
            acc[2][1] = ffma2(a2, u01.y, acc[2][1]);
            acc[3][1] = ffma2(a3, u01.y, acc[3][1]);
            acc[0][2] = ffma2(a0, u23.x, acc[0][2]);
            acc[1][2] = ffma2(a1, u23.x, acc[1][2]);
            acc[2][2] = ffma2(a2, u23.x, acc[2][2]);
            acc[3][2] = ffma2(a3, u23.x, acc[3][2]);
            acc[0][3] = ffma2(a0, u23.y, acc[0][3]);
            acc[1][3] = ffma2(a1, u23.y, acc[1][3]);
            acc[2][3] = ffma2(a2, u23.y, acc[2][3]);
            acc[3][3] = ffma2(a3, u23.y, acc[3][3]);
        }
        __syncthreads();
    }
#pragma unroll
    for (int jp = 0; jp < 4; ++jp) {
        float4 lo = make_float4(lo2(acc[0][jp]), lo2(acc[1][jp]), lo2(acc[2][jp]), lo2(acc[3][jp]));
        float4 hi = make_float4(hi2(acc[0][jp]), hi2(acc[1][jp]), hi2(acc[2][jp]), hi2(acc[3][jp]));
        size_t base = (size_t)t * Gsz + cb * 128;
        *(float4*)&g_xw[(base + c0 + 2 * jp) * 64 + b0]     = lo;
        *(float4*)&g_xw[(base + c0 + 2 * jp + 1) * 64 + b0] = hi;
    }
}

// ---- dual barriers: release-REDG arrive + acquire-poll wait ----
__device__ __forceinline__ void garrive(int g) {
    __syncthreads();
    if (threadIdx.x == 0) {
        asm volatile("red.release.gpu.add.u32 [%0], %1;" :: "l"(&g_cnt2[g * 32]), "r"(1u) : "memory");
    }
}
__device__ __forceinline__ void gwait(int g, unsigned target) {
    if (threadIdx.x == 0) {
        unsigned v;
        do {
            asm volatile("ld.acquire.gpu.u32 %0, [%1];" : "=r"(v) : "l"(&g_cnt2[g * 32]) : "memory");
        } while (v < target);
    }
    __syncthreads();
}

// Persistent recurrence — two interleaved batch-half recurrences per CTA.
// 128 CTAs = 128 col-groups (4 hidden units = 16 gate cols each), BOTH b-halves.
// Per half: 8 warps, warp w owns k in [64w,64w+64), k-paired lanes (kg2 = L>>4),
// lane tile 8b x 4c (16 FFMA2 per k-pair), bank-disjoint (h rows pad 36, U rows
// stride 16). Halves alternate: each barrier's wait+skew hides under the other
// half's ~4.5K cycles of work.
// Smem: Us[512][16] + hs[8][64][36] + part[8][16][36] + red[16][36] = ~124KB.
#define REC_SMEM_FLOATS (8192 + 18432 + 4608 + 576)

__global__ __launch_bounds__(256, 1) void lstm_rec_k(float* __restrict__ out) {
    extern __shared__ float sm[];
    float* Us   = sm;            // [512][16]
    float* hs   = sm + 8192;     // [w][64][36]
    float* part = sm + 26624;    // [w][16][36]
    float* red  = sm + 31232;    // [16][36]

    const int n   = blockIdx.x;        // cg 0..127
    const int tid = threadIdx.x;
    const int w   = tid >> 5;
    const int L   = tid & 31;
    const int kg2 = L >> 4;            // k parity within pair
    const int t16 = L & 15;
    const int b0  = (t16 & 3) * 8;     // 0,8,16,24
    const int c0  = (t16 >> 2) * 4;    // 0,4,8,12
    const int ub  = tid & 31;          // update role (tid<128): batch within half
    const int ujj = tid >> 5;          // update role: hidden-within-cg 0..3
    const int jbase = n * 4;

    // resident U slice [512][16]
    {
        const float4* Usrc = (const float4*)(g_Up + (size_t)n * 8192);
        float4* Udst = (float4*)Us;
        for (int i = tid; i < 2048; i += 256) Udst[i] = Usrc[i];
    }

    // zero h parity 0 for both halves (this CTA's 4j slice)
    if (tid < 128) {
        g_h[(jbase + ujj) * 64 + 0 * 32 + ub] = 0.0f;
        g_h[(jbase + ujj) * 64 + 1 * 32 + ub] = 0.0f;
    }
    float creg[2] = {0.0f, 0.0f}, hreg[2] = {0.0f, 0.0f};

    garrive(0);
    garrive(1);
    unsigned target = NB;

    float* hw = hs + w * 2304;              // warp staging area [64][36]
    const float* Uw = Us + (w * 64) * 16;   // warp's U rows

    for (int step = 0; step < Tsz; ++step) {
        const int p = step & 1;

        // prefetch xW for BOTH halves (in flight across waits)
        float xg[2][4];
        if (tid < 128) {
            const size_t xbase = (size_t)step * Gsz;
#pragma unroll
            for (int bh = 0; bh < 2; ++bh)
#pragma unroll
                for (int g = 0; g < 4; ++g)
                    xg[bh][g] = __ldcs(&g_xw[(xbase + g * Hsz + jbase + ujj) * 64 + bh * 32 + ub]);
        }

#pragma unroll
        for (int bh = 0; bh < 2; ++bh) {
            const float* hq = g_h + p * (Hsz * Bsz) + bh * 32;   // row stride 64

            gwait(bh, target);

            u64 acc[4][4];                  // [c][b-pair]
#pragma unroll
            for (int j = 0; j < 4; ++j)
#pragma unroll
                for (int i = 0; i < 4; ++i) acc[j][i] = 0ull;

            // ---- stage half A (rows [0,32) of warp slice) ----
            float4 pv[8];
#pragma unroll
            for (int m = 0; m < 8; ++m) {
                int idx = L + 32 * m; int r = idx >> 3, q = idx & 7;
                pv[m] = __ldcg((const float4*)(hq + (w * 64 + r) * 64) + q);
            }
#pragma unroll
            for (int m = 0; m < 8; ++m) {
                int idx = L + 32 * m; int r = idx >> 3, q = idx & 7;
                *(float4*)&hw[r * 36 + q * 4] = pv[m];
            }
            // LDG for rows [32,64) in flight under compute A
            float4 pw[8];
#pragma unroll
            for (int m = 0; m < 8; ++m) {
                int idx = L + 32 * m; int r = 32 + (idx >> 3), q = idx & 7;
                pw[m] = __ldcg((const float4*)(hq + (w * 64 + r) * 64) + q);
            }
            __syncwarp();

            // ---- compute A: k-pairs over rows [0,32) ----
#pragma unroll 8
            for (int i = 0; i < 16; ++i) {
                const int row = 2 * i + kg2;
                ulonglong2 hA = *(const ulonglong2*)&hw[row * 36 + b0];
                ulonglong2 hB = *(const ulonglong2*)&hw[row * 36 + b0 + 4];
                float4 uq = *(const float4*)&Uw[row * 16 + c0];
                u64 u0 = dup2(uq.x), u1 = dup2(uq.y), u2 = dup2(uq.z), u3 = dup2(uq.w);
                acc[0][0] = ffma2(hA.x, u0, acc[0][0]); acc[0][1] = ffma2(hA.y, u0, acc[0][1]);
                acc[0][2] = ffma2(hB.x, u0, acc[0][2]); acc[0][3] = ffma2(hB.y, u0, acc[0][3]);
                acc[1][0] = ffma2(hA.x, u1, acc[1][0]); acc[1][1] = ffma2(hA.y, u1, acc[1][1]);
                acc[1][2] = ffma2(hB.x, u1, acc[1][2]); acc[1][3] = ffma2(hB.y, u1, acc[1][3]);
                acc[2][0] = ffma2(hA.x, u2, acc[2][0]); acc[2][1] = ffma2(hA.y, u2, acc[2][1]);
                acc[2][2] = ffma2(hB.x, u2, acc[2][2]); acc[2][3] = ffma2(hB.y, u2, acc[2][3]);
                acc[3][0] = ffma2(hA.x, u3, acc[3][0]); acc[3][1] = ffma2(hA.y, u3, acc[3][1]);
                acc[3][2] = ffma2(hB.x, u3, acc[3][2]); acc[3][3] = ffma2(hB.y, u3, acc[3][3]);
            }

            // ---- stage rows [32,64) ----
#pragma unroll
            for (int m = 0; m < 8; ++m) {
                int idx = L + 32 * m; int r = 32 + (idx >> 3), q = idx & 7;
                *(float4*)&hw[r * 36 + q * 4] = pw[m];
            }
            __syncwarp();

            // ---- compute B: k-pairs over rows [32,64) ----
#pragma unroll 8
            for (int i = 16; i < 32; ++i) {
                const int row = 2 * i + kg2;
                ulonglong2 hA = *(const ulonglong2*)&hw[row * 36 + b0];
                ulonglong2 hB = *(const ulonglong2*)&hw[row * 36 + b0 + 4];
                float4 uq = *(const float4*)&Uw[row * 16 + c0];
                u64 u0 = dup2(uq.x), u1 = dup2(uq.y), u2 = dup2(uq.z), u3 = dup2(uq.w);
                acc[0][0] = ffma2(hA.x, u0, acc[0][0]); acc[0][1] = ffma2(hA.y, u0, acc[0][1]);
                acc[0][2] = ffma2(hB.x, u0, acc[0][2]); acc[0][3] = ffma2(hB.y, u0, acc[0][3]);
                acc[1][0] = ffma2(hA.x, u1, acc[1][0]); acc[1][1] = ffma2(hA.y, u1, acc[1][1]);
                acc[1][2] = ffma2(hB.x, u1, acc[1][2]); acc[1][3] = ffma2(hB.y, u1, acc[1][3]);
                acc[2][0] = ffma2(hA.x, u2, acc[2][0]); acc[2][1] = ffma2(hA.y, u2, acc[2][1]);
                acc[2][2] = ffma2(hB.x, u2, acc[2][2]); acc[2][3] = ffma2(hB.y, u2, acc[2][3]);
                acc[3][0] = ffma2(hA.x, u3, acc[3][0]); acc[3][1] = ffma2(hA.y, u3, acc[3][1]);
                acc[3][2] = ffma2(hB.x, u3, acc[3][2]); acc[3][3] = ffma2(hB.y, u3, acc[3][3]);
            }

            // ---- merge the two k-groups inside the warp (SHFL path) ----
#pragma unroll
            for (int j = 0; j < 4; ++j)
#pragma unroll
                for (int i = 0; i < 4; ++i)
                    acc[j][i] = fadd2(acc[j][i], __shfl_xor_sync(0xffffffffu, acc[j][i], 16));

            // per-warp partial tile [16c][32b]; lanes 0-15 hold merged sums
            if (kg2 == 0) {
#pragma unroll
                for (int j = 0; j < 4; ++j) {
                    float* pp = part + w * 576 + (c0 + j) * 36 + b0;
                    *(ulonglong2*)pp       = make_ulonglong2(acc[j][0], acc[j][1]);
                    *(ulonglong2*)(pp + 4) = make_ulonglong2(acc[j][2], acc[j][3]);
                }
            }
            __syncthreads();

            // reduce over 8 warps: thread -> col rc = tid>>4 (0..15), b-pair rq
            {
                const int rc = tid >> 4, rq = (tid & 15) * 2;
                u64 s = *(const u64*)&part[rc * 36 + rq];
#pragma unroll
                for (int ww = 1; ww < 8; ++ww)
                    s = fadd2(s, *(const u64*)&part[ww * 576 + rc * 36 + rq]);
                *(u64*)&red[rc * 36 + rq] = s;
            }
            __syncthreads();

            // elementwise update: tid<128 owns (b = bh*32+ub, j = jbase+ujj)
            if (tid < 128) {
                float v0 = red[(0 * 4 + ujj) * 36 + ub] + xg[bh][0];
                float v1 = red[(1 * 4 + ujj) * 36 + ub] + xg[bh][1];
                float v2 = red[(2 * 4 + ujj) * 36 + ub] + xg[bh][2];
                float v3 = red[(3 * 4 + ujj) * 36 + ub] + xg[bh][3];
                float ig = 1.0f / (1.0f + __expf(-v0));
                float fg = 1.0f / (1.0f + __expf(-v1));
                float gg = tanhf(v2);
                float og = 1.0f / (1.0f + __expf(-v3));
                creg[bh] = fg * creg[bh] + ig * gg;
                hreg[bh] = og * tanhf(creg[bh]);
                __stcg(&g_h[(p ^ 1) * (Hsz * Bsz) + (jbase + ujj) * 64 + bh * 32 + ub], hreg[bh]);
            }

            garrive(bh);
        }

        target += NB;
    }

    if (tid < 128) {
#pragma unroll
        for (int bh = 0; bh < 2; ++bh) {
            out[(bh * 32 + ub) * Hsz + jbase + ujj] = hreg[bh];
            out[Bsz * Hsz + (bh * 32 + ub) * Hsz + jbase + ujj] = creg[bh];
        }
    }
}

extern "C" void kernel_launch(void* const* d_in, const int* in_sizes, int n_in,
                              void* d_out, int out_size) {
    const float* x    = (const float*)d_in[0];
    const float* W    = (const float*)d_in[1];
    const float* U    = (const float*)d_in[2];
    const float* bias = (const float*)d_in[3];
    float* out = (float*)d_out;
    (void)in_sizes; (void)n_in; (void)out_size;

    static int smem_set = 0;
    if (!smem_set) {
        cudaFuncSetAttribute(lstm_rec_k, cudaFuncAttributeMaxDynamicSharedMemorySize,
                             REC_SMEM_FLOATS * 4);
        smem_set = 1;
    }

    pack_U_k<<<2048, 512>>>(U);
    dim3 g(16, Tsz);
    gemm_xw_k<<<g, 256>>>(x, W, bias);
    reset_bar_k<<<1, 64>>>();
    lstm_rec_k<<<NB, 256, REC_SMEM_FLOATS * 4>>>(out);
}

// round 12
// speedup vs baseline: 1.3302x; 1.3302x over previous
#include <cuda_runtime.h>
#include <math.h>

#define Bsz 64
#define Tsz 2048
#define Dsz 256
#define Hsz 512
#define Gsz 2048
#define NB  128
#define GRP 64

typedef unsigned long long u64;

// ---- packed fp32x2 helpers (Blackwell FFMA2/FADD2, PTX-only) ----
__device__ __forceinline__ u64 ffma2(u64 a, u64 b, u64 c) {
    u64 d;
    asm("fma.rn.f32x2 %0, %1, %2, %3;" : "=l"(d) : "l"(a), "l"(b), "l"(c));
    return d;
}
__device__ __forceinline__ u64 dup2(float x) {
    u64 d;
    asm("mov.b64 %0, {%1, %1};" : "=l"(d) : "r"(__float_as_uint(x)));
    return d;
}
__device__ __forceinline__ float lo2(u64 d) { return __int_as_float((int)(unsigned)(d & 0xffffffffu)); }
__device__ __forceinline__ float hi2(u64 d) { return __int_as_float((int)(unsigned)(d >> 32)); }

// Scratch (device globals)
__device__ float g_xw[(size_t)Tsz * Gsz * Bsz];    // [t][col][b]  1 GiB
__device__ float g_Up[64 * Hsz * 32];              // [cg][k][c]   4 MB
__device__ float g_h[2 * Hsz * Bsz];               // [parity][j][b]
__device__ unsigned g_cnt2[64];                    // 2 counters, 128B apart

__global__ void reset_bar_k() { if (threadIdx.x < 64) g_cnt2[threadIdx.x] = 0u; }

// g_Up[cg][k][c] = U[k][gate*512 + cg*8 + jj], c = gate*8 + jj  (32 cols per cg)
__global__ void pack_U_k(const float* __restrict__ U) {
    int idx = blockIdx.x * blockDim.x + threadIdx.x;   // 2^20 total
    int c  = idx & 31;
    int k  = (idx >> 5) & (Hsz - 1);
    int cg = idx >> 14;
    g_Up[idx] = U[k * Gsz + (c >> 3) * Hsz + cg * 8 + (c & 7)];
}

// xW GEMM with FFMA2: C[b][col] = sum_k x[b,t,k]*W[k,col] + bias[col] -> [t][col][b]
__global__ __launch_bounds__(256, 2) void gemm_xw_k(const float* __restrict__ x,
                                                    const float* __restrict__ W,
                                                    const float* __restrict__ bias) {
    const int t   = blockIdx.y;
    const int cb  = blockIdx.x;
    const int tid = threadIdx.x;
    __shared__ float As[32 * 68];
    __shared__ float Bs[32 * 132];
    const int b0 = (tid & 15) * 4;
    const int c0 = (tid >> 4) * 8;

    u64 acc[4][4];
    {
        ulonglong2 bb0 = *(const ulonglong2*)(bias + cb * 128 + c0);
        ulonglong2 bb1 = *(const ulonglong2*)(bias + cb * 128 + c0 + 4);
#pragma unroll
        for (int i = 0; i < 4; ++i) {
            acc[i][0] = bb0.x; acc[i][1] = bb0.y;
            acc[i][2] = bb1.x; acc[i][3] = bb1.y;
        }
    }
    const int arow = tid >> 3;
    const int af4  = tid & 7;
    const int wk   = tid >> 3;
    const int wc   = (tid & 7) * 16;

    for (int k0 = 0; k0 < Dsz; k0 += 32) {
#pragma unroll
        for (int pass = 0; pass < 2; ++pass) {
            int b = arow + pass * 32;
            float4 v = *(const float4*)(x + ((size_t)b * Tsz + t) * Dsz + k0 + af4 * 4);
            As[(af4 * 4 + 0) * 68 + b] = v.x;
            As[(af4 * 4 + 1) * 68 + b] = v.y;
            As[(af4 * 4 + 2) * 68 + b] = v.z;
            As[(af4 * 4 + 3) * 68 + b] = v.w;
        }
        const float* wp = W + (size_t)(k0 + wk) * Gsz + cb * 128 + wc;
        float4 w0 = ((const float4*)wp)[0];
        float4 w1 = ((const float4*)wp)[1];
        float4 w2 = ((const float4*)wp)[2];
        float4 w3 = ((const float4*)wp)[3];
        *(float4*)&Bs[wk * 132 + wc + 0]  = w0;
        *(float4*)&Bs[wk * 132 + wc + 4]  = w1;
        *(float4*)&Bs[wk * 132 + wc + 8]  = w2;
        *(float4*)&Bs[wk * 132 + wc + 12] = w3;
        __syncthreads();
#pragma unroll
        for (int kk = 0; kk < 32; ++kk) {
            float4 a = *(const float4*)&As[kk * 68 + b0];
            ulonglong2 u01 = *(const ulonglong2*)&Bs[kk * 132 + c0];
            ulonglong2 u23 = *(const ulonglong2*)&Bs[kk * 132 + c0 + 4];
            u64 a0 = dup2(a.x), a1 = dup2(a.y), a2 = dup2(a.z), a3 = dup2(a.w);
            acc[0][0] = ffma2(a0, u01.x, acc[0][0]);
            acc[1][0] = ffma2(a1, u01.x, acc[1][0]);
            acc[2][0] = ffma2(a2, u01.x, acc[2][0]);
            acc[3][0] = ffma2(a3, u01.x, acc[3][0]);
            acc[0][1] = ffma2(a0, u01.y, acc[0][1]);
            acc[1][1] = ffma2(a1, u01.y, acc[1][1]);
            acc[2][1] = ffma2(a2, u01.y, acc[2][1]);
            acc[3][1] = ffma2(a3, u01.y, acc[3][1]);
            acc[0][2] = ffma2(a0, u23.x, acc[0][2]);
            acc[1][2] = ffma2(a1, u23.x, acc[1][2]);
            acc[2][2] = ffma2(a2, u23.x, acc[2][2]);
            acc[3][2] = ffma2(a3, u23.x, acc[3][2]);
            acc[0][3] = ffma2(a0, u23.y, acc[0][3]);
            acc[1][3] = ffma2(a1, u23.y, acc[1][3]);
            acc[2][3] = ffma2(a2, u23.y, acc[2][3]);
            acc[3][3] = ffma2(a3, u23.y, acc[3][3]);
        }
        __syncthreads();
    }
#pragma unroll
    for (int jp = 0; jp < 4; ++jp) {
        float4 lo = make_float4(lo2(acc[0][jp]), lo2(acc[1][jp]), lo2(acc[2][jp]), lo2(acc[3][jp]));
        float4 hi = make_float4(hi2(acc[0][jp]), hi2(acc[1][jp]), hi2(acc[2][jp]), hi2(acc[3][jp]));
        size_t base = (size_t)t * Gsz + cb * 128;
        *(float4*)&g_xw[(base + c0 + 2 * jp) * 64 + b0]     = lo;
        *(float4*)&g_xw[(base + c0 + 2 * jp + 1) * 64 + b0] = hi;
    }
}

// ---- dual 64-CTA group barriers: release-REDG arrive + acquire-poll wait ----
__device__ __forceinline__ void garrive(int g) {
    __syncthreads();
    if (threadIdx.x == 0) {
        asm volatile("red.release.gpu.add.u32 [%0], %1;" :: "l"(&g_cnt2[g * 32]), "r"(1u) : "memory");
    }
}
__device__ __forceinline__ void gwait(int g, unsigned target) {
    if (threadIdx.x == 0) {
        unsigned v;
        do {
            asm volatile("ld.acquire.gpu.u32 %0, [%1];" : "=r"(v) : "l"(&g_cnt2[g * 32]) : "memory");
        } while (v < target);
    }
    __syncthreads();
}

// Persistent recurrence — R7 skeleton, split barrier groups + fused reduce/update.
// 128 CTAs = (b-half bh) x (64 col-groups cg: 8 hidden units = 32 gate cols).
// Each CTA touches ONLY its bh half of h -> the two 64-CTA groups are fully
// independent; separate barriers de-correlate skew and halve arrival count.
// 8 warps; warp w owns k in [64w, 64w+64), staged warp-locally in two 32-row
// halves (LDG-B hidden under compute-A). Tile 8b x 4c, 16 FFMA2/k.
// Reduce+update FUSED: each thread sums its 8 warp-partials directly (32 scalar
// LDS, bank = lane, conflict-free) — one less __syncthreads, no red buffer.
// Smem: Us[512][32] + hs[8][64][32] + part[8][32][32] = 160KB.
#define REC_SMEM_FLOATS (16384 + 16384 + 8192)

__global__ __launch_bounds__(256, 1) void lstm_rec_k(float* __restrict__ out) {
    extern __shared__ float sm[];
    float* Us   = sm;            // [512][32]
    float* hs   = sm + 16384;    // [w][64][32]
    float* part = sm + 32768;    // [w][32c][32b]

    const int n   = blockIdx.x;
    const int tid = threadIdx.x;
    const int bh  = n & 1;
    const int cg  = n >> 1;
    const int w   = tid >> 5;
    const int L   = tid & 31;
    const int b0  = (L & 3) * 8;
    const int c0  = (L >> 2) * 4;
    const int ub  = tid & 31;          // update role: batch within half
    const int ujj = tid >> 5;          // update role: hidden-within-cg 0..7
    const int jbase = cg * 8;

    // resident U slice [512][32]
    {
        const float4* Usrc = (const float4*)(g_Up + (size_t)cg * 16384);
        float4* Udst = (float4*)Us;
        for (int i = tid; i < 4096; i += 256) Udst[i] = Usrc[i];
    }

    // zero h parity 0 (this CTA's slice)
    g_h[(jbase + ujj) * 64 + bh * 32 + ub] = 0.0f;
    float creg = 0.0f, hreg = 0.0f;

    unsigned target = GRP;
    garrive(bh);

    float* hw = hs + w * 2048;         // this warp's staging area [64][32]

    for (int step = 0; step < Tsz; ++step) {
        const int p = step & 1;
        const float* hq = g_h + p * (Hsz * Bsz) + bh * 32;   // row stride 64

        // xW loads in flight across the barrier wait
        const size_t xbase = (size_t)step * Gsz;
        float xg0 = __ldcs(&g_xw[(xbase + 0 * Hsz + jbase + ujj) * 64 + bh * 32 + ub]);
        float xg1 = __ldcs(&g_xw[(xbase + 1 * Hsz + jbase + ujj) * 64 + bh * 32 + ub]);
        float xg2 = __ldcs(&g_xw[(xbase + 2 * Hsz + jbase + ujj) * 64 + bh * 32 + ub]);
        float xg3 = __ldcs(&g_xw[(xbase + 3 * Hsz + jbase + ujj) * 64 + bh * 32 + ub]);

        gwait(bh, target);
        target += GRP;

        u64 acc[16];
#pragma unroll
        for (int j = 0; j < 16; ++j) acc[j] = 0ull;

        // ---- stage half A (rows [64w, 64w+32)) ----
        float4 pv[8];
#pragma unroll
        for (int m = 0; m < 8; ++m) {
            int idx = L + 32 * m; int r = idx >> 3, q = idx & 7;
            pv[m] = __ldcg((const float4*)(hq + (w * 64 + r) * 64) + q);
        }
#pragma unroll
        for (int m = 0; m < 8; ++m) {
            int idx = L + 32 * m; int r = idx >> 3, q = idx & 7;
            *(float4*)&hw[r * 32 + q * 4] = pv[m];
        }
        // issue LDG for half B (latency hides under compute A)
        float4 pw[8];
#pragma unroll
        for (int m = 0; m < 8; ++m) {
            int idx = L + 32 * m; int r = 32 + (idx >> 3), q = idx & 7;
            pw[m] = __ldcg((const float4*)(hq + (w * 64 + r) * 64) + q);
        }
        __syncwarp();

        // ---- compute half A ----
#pragma unroll 16
        for (int i = 0; i < 32; ++i) {
            ulonglong2 hA = *(const ulonglong2*)&hw[i * 32 + b0];
            ulonglong2 hB = *(const ulonglong2*)&hw[i * 32 + b0 + 4];
            float4 uq = *(const float4*)&Us[(w * 64 + i) * 32 + c0];
            u64 u0 = dup2(uq.x), u1 = dup2(uq.y), u2 = dup2(uq.z), u3 = dup2(uq.w);
            acc[0]  = ffma2(hA.x, u0, acc[0]);
            acc[1]  = ffma2(hA.y, u0, acc[1]);
            acc[2]  = ffma2(hB.x, u0, acc[2]);
            acc[3]  = ffma2(hB.y, u0, acc[3]);
            acc[4]  = ffma2(hA.x, u1, acc[4]);
            acc[5]  = ffma2(hA.y, u1, acc[5]);
            acc[6]  = ffma2(hB.x, u1, acc[6]);
            acc[7]  = ffma2(hB.y, u1, acc[7]);
            acc[8]  = ffma2(hA.x, u2, acc[8]);
            acc[9]  = ffma2(hA.y, u2, acc[9]);
            acc[10] = ffma2(hB.x, u2, acc[10]);
            acc[11] = ffma2(hB.y, u2, acc[11]);
            acc[12] = ffma2(hA.x, u3, acc[12]);
            acc[13] = ffma2(hA.y, u3, acc[13]);
            acc[14] = ffma2(hB.x, u3, acc[14]);
            acc[15] = ffma2(hB.y, u3, acc[15]);
        }

        // ---- stage half B ----
#pragma unroll
        for (int m = 0; m < 8; ++m) {
            int idx = L + 32 * m; int r = 32 + (idx >> 3), q = idx & 7;
            *(float4*)&hw[r * 32 + q * 4] = pw[m];
        }
        __syncwarp();

        // ---- compute half B ----
#pragma unroll 16
        for (int i = 32; i < 64; ++i) {
            ulonglong2 hA = *(const ulonglong2*)&hw[i * 32 + b0];
            ulonglong2 hB = *(const ulonglong2*)&hw[i * 32 + b0 + 4];
            float4 uq = *(const float4*)&Us[(w * 64 + i) * 32 + c0];
            u64 u0 = dup2(uq.x), u1 = dup2(uq.y), u2 = dup2(uq.z), u3 = dup2(uq.w);
            acc[0]  = ffma2(hA.x, u0, acc[0]);
            acc[1]  = ffma2(hA.y, u0, acc[1]);
            acc[2]  = ffma2(hB.x, u0, acc[2]);
            acc[3]  = ffma2(hB.y, u0, acc[3]);
            acc[4]  = ffma2(hA.x, u1, acc[4]);
            acc[5]  = ffma2(hA.y, u1, acc[5]);
            acc[6]  = ffma2(hB.x, u1, acc[6]);
            acc[7]  = ffma2(hB.y, u1, acc[7]);
            acc[8]  = ffma2(hA.x, u2, acc[8]);
            acc[9]  = ffma2(hA.y, u2, acc[9]);
            acc[10] = ffma2(hB.x, u2, acc[10]);
            acc[11] = ffma2(hB.y, u2, acc[11]);
            acc[12] = ffma2(hA.x, u3, acc[12]);
            acc[13] = ffma2(hA.y, u3, acc[13]);
            acc[14] = ffma2(hB.x, u3, acc[14]);
            acc[15] = ffma2(hB.y, u3, acc[15]);
        }

        // per-warp partial tile [32c][32b] (own region)
#pragma unroll
        for (int j = 0; j < 4; ++j) {
            float* pp = part + w * 1024 + (c0 + j) * 32 + b0;
            *(ulonglong2*)pp       = make_ulonglong2(acc[4 * j + 0], acc[4 * j + 1]);
            *(ulonglong2*)(pp + 4) = make_ulonglong2(acc[4 * j + 2], acc[4 * j + 3]);
        }
        __syncthreads();

        // FUSED reduce + update: thread (b = ub, j = jbase + ujj) sums its own
        // 8 warp-partials per gate (bank = ub -> conflict-free scalar LDS)
        float v[4];
#pragma unroll
        for (int g = 0; g < 4; ++g) {
            const float* pp = part + (g * 8 + ujj) * 32 + ub;
            float s = pp[0];
#pragma unroll
            for (int ww = 1; ww < 8; ++ww) s += pp[ww * 1024];
            v[g] = s;
        }
        float ig = 1.0f / (1.0f + __expf(-(v[0] + xg0)));
        float fg = 1.0f / (1.0f + __expf(-(v[1] + xg1)));
        float gg = tanhf(v[2] + xg2);
        float og = 1.0f / (1.0f + __expf(-(v[3] + xg3)));
        creg = fg * creg + ig * gg;
        hreg = og * tanhf(creg);
        __stcg(&g_h[(p ^ 1) * (Hsz * Bsz) + (jbase + ujj) * 64 + bh * 32 + ub], hreg);

        garrive(bh);
    }

    out[(bh * 32 + ub) * Hsz + jbase + ujj] = hreg;
    out[Bsz * Hsz + (bh * 32 + ub) * Hsz + jbase + ujj] = creg;
}

extern "C" void kernel_launch(void* const* d_in, const int* in_sizes, int n_in,
                              void* d_out, int out_size) {
    const float* x    = (const float*)d_in[0];
    const float* W    = (const float*)d_in[1];
    const float* U    = (const float*)d_in[2];
    const float* bias = (const float*)d_in[3];
    float* out = (float*)d_out;
    (void)in_sizes; (void)n_in; (void)out_size;

    static int smem_set = 0;
    if (!smem_set) {
        cudaFuncSetAttribute(lstm_rec_k, cudaFuncAttributeMaxDynamicSharedMemorySize,
                             REC_SMEM_FLOATS * 4);
        smem_set = 1;
    }

    pack_U_k<<<2048, 512>>>(U);
    dim3 g(16, Tsz);
    gemm_xw_k<<<g, 256>>>(x, W, bias);
    reset_bar_k<<<1, 64>>>();
    lstm_rec_k<<<NB, 256, REC_SMEM_FLOATS * 4>>>(out);
}